// round 16
// baseline (speedup 1.0000x reference)
#include <cuda_runtime.h>
#include <cuda_bf16.h>
#include <cstdint>

#define T_SEQ 2048
#define NHEAD 16
#define HD 64
#define CDIM 1024
#define BSZ 4
#define MROWS 8192

// ---------------- device scratch (allocation-free rule) ----------------
#define QKV_ELEMS ((size_t)BSZ * NHEAD * T_SEQ * HD)
__device__ __align__(128) __nv_bfloat16 g_qh[QKV_ELEMS], g_ql[QKV_ELEMS];
__device__ __align__(128) __nv_bfloat16 g_kh[QKV_ELEMS], g_kl[QKV_ELEMS];
__device__ __align__(128) __nv_bfloat16 g_vh[QKV_ELEMS], g_vl[QKV_ELEMS];
__device__ __align__(128) __nv_bfloat16 g_xh[(size_t)MROWS * CDIM], g_xl[(size_t)MROWS * CDIM];
__device__ __align__(128) __nv_bfloat16 g_wh[(size_t)3 * CDIM * CDIM], g_wl[(size_t)3 * CDIM * CDIM];
__device__ __align__(128) __nv_bfloat16 g_wph[(size_t)CDIM * CDIM], g_wpl[(size_t)CDIM * CDIM];
__device__ __align__(128) __nv_bfloat16 g_yh[(size_t)MROWS * CDIM], g_yl[(size_t)MROWS * CDIM];

// ---------------- helpers ----------------
__device__ __forceinline__ uint32_t smem_to_u32(const void* p) {
    uint32_t a;
    asm("{ .reg .u64 t; cvta.to.shared.u64 t, %1; cvt.u32.u64 %0, t; }" : "=r"(a) : "l"(p));
    return a;
}

#define LDSM4(r, addr) \
    asm volatile("ldmatrix.sync.aligned.m8n8.x4.shared.b16 {%0,%1,%2,%3}, [%4];" \
                 : "=r"((r)[0]), "=r"((r)[1]), "=r"((r)[2]), "=r"((r)[3]) : "r"(addr))
#define LDSM4T(r, addr) \
    asm volatile("ldmatrix.sync.aligned.m8n8.x4.trans.shared.b16 {%0,%1,%2,%3}, [%4];" \
                 : "=r"((r)[0]), "=r"((r)[1]), "=r"((r)[2]), "=r"((r)[3]) : "r"(addr))
#define CP16(dst, src) \
    asm volatile("cp.async.cg.shared.global [%0], [%1], 16;" :: "r"(dst), "l"(src))
#define CP_COMMIT() asm volatile("cp.async.commit_group;" ::: "memory")
#define CP_WAIT(n) asm volatile("cp.async.wait_group %0;" :: "n"(n) : "memory")

__device__ __forceinline__ void bsplit(float x, __nv_bfloat16& h, __nv_bfloat16& l) {
    h = __float2bfloat16_rn(x);
    l = __float2bfloat16_rn(x - __bfloat162float(h));
}
__device__ __forceinline__ void bsplit2(float x, float y, uint32_t& hp, uint32_t& lp) {
    __nv_bfloat162 hb = __floats2bfloat162_rn(x, y);
    float hx = __bfloat162float(__low2bfloat16(hb));
    float hy = __bfloat162float(__high2bfloat16(hb));
    __nv_bfloat162 lb = __floats2bfloat162_rn(x - hx, y - hy);
    hp = *reinterpret_cast<uint32_t*>(&hb);
    lp = *reinterpret_cast<uint32_t*>(&lb);
}

__device__ __forceinline__ void mma16(float c[4],
                                      uint32_t a0, uint32_t a1, uint32_t a2, uint32_t a3,
                                      uint32_t b0, uint32_t b1) {
    asm("mma.sync.aligned.m16n8k16.row.col.f32.bf16.bf16.f32 "
        "{%0,%1,%2,%3}, {%4,%5,%6,%7}, {%8,%9}, {%0,%1,%2,%3};\n"
        : "+f"(c[0]), "+f"(c[1]), "+f"(c[2]), "+f"(c[3])
        : "r"(a0), "r"(a1), "r"(a2), "r"(a3), "r"(b0), "r"(b1));
}

// QKV epilogue: write pre-split bf16 h/l, Q scaled by 1/8
__device__ __forceinline__ void qkv_store_bf(int m, int n, float v0, float v1) {
    int part = n >> 10;
    int cc = n & 1023;
    int h = cc >> 6, d = cc & 63;
    int b = m >> 11, t = m & 2047;
    if (part == 0) { v0 *= 0.125f; v1 *= 0.125f; }
    __nv_bfloat16* dh = (part == 0) ? g_qh : (part == 1) ? g_kh : g_vh;
    __nv_bfloat16* dl = (part == 0) ? g_ql : (part == 1) ? g_kl : g_vl;
    size_t off = ((((size_t)b * NHEAD + h) * T_SEQ + t) << 6) + d;
    uint32_t hp, lp;
    bsplit2(v0, v1, hp, lp);
    *reinterpret_cast<uint32_t*>(dh + off) = hp;
    *reinterpret_cast<uint32_t*>(dl + off) = lp;
}

// ---------------- pre-kernels ----------------
__global__ void xsplit_kernel(const float* __restrict__ X, __nv_bfloat16* __restrict__ Xh,
                              __nv_bfloat16* __restrict__ Xl) {
    int i = blockIdx.x * blockDim.x + threadIdx.x;
    float4 v = reinterpret_cast<const float4*>(X)[i];
    uint32_t h01, l01, h23, l23;
    bsplit2(v.x, v.y, h01, l01);
    bsplit2(v.z, v.w, h23, l23);
    reinterpret_cast<uint2*>(Xh)[i] = make_uint2(h01, h23);
    reinterpret_cast<uint2*>(Xl)[i] = make_uint2(l01, l23);
}

__global__ void wsplit_kernel(const float* __restrict__ W, __nv_bfloat16* __restrict__ Wh,
                              __nv_bfloat16* __restrict__ Wl, int N) {
    __shared__ float tile[32][33];
    const int nb = blockIdx.x * 32, kb = blockIdx.y * 32;
    const int tx = threadIdx.x, ty = threadIdx.y;
#pragma unroll
    for (int r = 0; r < 32; r += 8)
        tile[ty + r][tx] = W[(size_t)(kb + ty + r) * N + nb + tx];
    __syncthreads();
#pragma unroll
    for (int r = 0; r < 32; r += 8) {
        float v = tile[tx][ty + r];
        __nv_bfloat16 h, l;
        bsplit(v, h, l);
        size_t o = (size_t)(nb + ty + r) * CDIM + kb + tx;
        Wh[o] = h;
        Wl[o] = l;
    }
}

// ---------------------------------------------------------------------------
// bf16 3-term GEMM (LOCKED: exact R8 config, best measured 468 us).
// ---------------------------------------------------------------------------
#define GEMM_SMEM_BYTES (2 * 40960)  // 81920

template <int NTOT, int MODE>
__global__ __launch_bounds__(512, 1) void gemm_bf16(
    const __nv_bfloat16* __restrict__ Ah_g, const __nv_bfloat16* __restrict__ Al_g,
    const __nv_bfloat16* __restrict__ Bh_g, const __nv_bfloat16* __restrict__ Bl_g,
    const float* __restrict__ bias, float* __restrict__ out) {
    extern __shared__ char smem[];
    const uint32_t sb_u = smem_to_u32(smem);
    const int tid = threadIdx.x, lane = tid & 31, warp = tid >> 5;
    const int wm = (warp >> 2) * 32, wn = (warp & 3) * 32;
    const int m0 = blockIdx.x * 128, n0 = blockIdx.y * 128;
    const int kp = lane & 3, r4 = lane >> 2;
    const int l16 = lane & 15, lhi = lane >> 4;

    const uint32_t a_fa = (uint32_t)(wm + l16) * 80 + lhi * 16;
    const uint32_t b_fa = (uint32_t)(wn + l16) * 80 + lhi * 16;

    const int lr = tid >> 2, ch = tid & 3;
    const uint32_t sbyte = (uint32_t)lr * 80 + (uint32_t)ch * 16;
    const __nv_bfloat16* pAh = Ah_g + (size_t)(m0 + lr) * CDIM + ch * 8;
    const __nv_bfloat16* pAl = Al_g + (size_t)(m0 + lr) * CDIM + ch * 8;
    const __nv_bfloat16* pBh = Bh_g + (size_t)(n0 + lr) * CDIM + ch * 8;
    const __nv_bfloat16* pBl = Bl_g + (size_t)(n0 + lr) * CDIM + ch * 8;

    float acc[2][4][4];
#pragma unroll
    for (int i = 0; i < 2; i++)
#pragma unroll
        for (int j = 0; j < 4; j++)
#pragma unroll
            for (int r = 0; r < 4; r++) acc[i][j][r] = 0.f;

    uint4 va, vb, vc, vd;
    va = *reinterpret_cast<const uint4*>(pAh);
    vb = *reinterpret_cast<const uint4*>(pAl);
    vc = *reinterpret_cast<const uint4*>(pBh);
    vd = *reinterpret_cast<const uint4*>(pBl);
    *reinterpret_cast<uint4*>(smem + sbyte) = va;
    *reinterpret_cast<uint4*>(smem + 10240 + sbyte) = vb;
    *reinterpret_cast<uint4*>(smem + 20480 + sbyte) = vc;
    *reinterpret_cast<uint4*>(smem + 30720 + sbyte) = vd;
    __syncthreads();

    const int NK = CDIM / 32;
    for (int kt = 0; kt < NK; kt++) {
        const int buf = kt & 1;
        const bool more = (kt + 1 < NK);
        if (more) {
            const int kk = (kt + 1) * 32;
            va = *reinterpret_cast<const uint4*>(pAh + kk);
            vb = *reinterpret_cast<const uint4*>(pAl + kk);
            vc = *reinterpret_cast<const uint4*>(pBh + kk);
            vd = *reinterpret_cast<const uint4*>(pBl + kk);
        }

        const uint32_t base_u = sb_u + buf * 40960;
#pragma unroll
        for (int ks = 0; ks < 2; ks++) {
            const uint32_t ko = ks * 32;
            uint32_t ah[2][4], al[2][4], bh[2][4], bl[2][4];
#pragma unroll
            for (int i = 0; i < 2; i++) {
                LDSM4(ah[i], base_u + a_fa + i * 1280 + ko);
                LDSM4(al[i], base_u + 10240 + a_fa + i * 1280 + ko);
            }
#pragma unroll
            for (int jp = 0; jp < 2; jp++) {
                LDSM4(bh[jp], base_u + 20480 + b_fa + jp * 1280 + ko);
                LDSM4(bl[jp], base_u + 30720 + b_fa + jp * 1280 + ko);
            }
            // term-major: all hh, then all hl, then all lh
#pragma unroll
            for (int j = 0; j < 4; j++) {
                const int jp = j >> 1, sel = j & 1;
#pragma unroll
                for (int i = 0; i < 2; i++)
                    mma16(acc[i][j], ah[i][0], ah[i][1], ah[i][2], ah[i][3],
                          bh[jp][sel], bh[jp][2 + sel]);
            }
#pragma unroll
            for (int j = 0; j < 4; j++) {
                const int jp = j >> 1, sel = j & 1;
#pragma unroll
                for (int i = 0; i < 2; i++)
                    mma16(acc[i][j], ah[i][0], ah[i][1], ah[i][2], ah[i][3],
                          bl[jp][sel], bl[jp][2 + sel]);
            }
#pragma unroll
            for (int j = 0; j < 4; j++) {
                const int jp = j >> 1, sel = j & 1;
#pragma unroll
                for (int i = 0; i < 2; i++)
                    mma16(acc[i][j], al[i][0], al[i][1], al[i][2], al[i][3],
                          bh[jp][sel], bh[jp][2 + sel]);
            }
        }

        if (more) {
            char* nb2 = smem + (1 - buf) * 40960;
            *reinterpret_cast<uint4*>(nb2 + sbyte) = va;
            *reinterpret_cast<uint4*>(nb2 + 10240 + sbyte) = vb;
            *reinterpret_cast<uint4*>(nb2 + 20480 + sbyte) = vc;
            *reinterpret_cast<uint4*>(nb2 + 30720 + sbyte) = vd;
        }
        __syncthreads();
    }

    // Epilogue
#pragma unroll
    for (int i = 0; i < 2; i++) {
        int row = m0 + wm + i * 16 + r4;
#pragma unroll
        for (int j = 0; j < 4; j++) {
            int col = n0 + wn + j * 8 + kp * 2;
            float b0 = bias[col], b1 = bias[col + 1];
            float v00 = acc[i][j][0] + b0, v01 = acc[i][j][1] + b1;
            float v10 = acc[i][j][2] + b0, v11 = acc[i][j][3] + b1;
            if (MODE == 0) {
                qkv_store_bf(row, col, v00, v01);
                qkv_store_bf(row + 8, col, v10, v11);
            } else {
                *reinterpret_cast<float2*>(out + (size_t)row * NTOT + col) = make_float2(v00, v01);
                *reinterpret_cast<float2*>(out + (size_t)(row + 8) * NTOT + col) = make_float2(v10, v11);
            }
        }
    }
}

// ---------------------------------------------------------------------------
// Flash attention: key-tile 128 (one softmax + one barrier pair per 128 keys),
// Q-tile 128, 8 warps x 16 q-rows, Q fragments hoisted, cp.async 2-stage ring,
// heavy-first q order, P aliased into dead S regs, V via ldmatrix.trans.
// smem: Qh/Ql 36864 + 2 stages x {Kh,Kl,Vh,Vl}[128][72] (73728) = 184320 B.
// ---------------------------------------------------------------------------
#define ATT_SMEM_BYTES 184320

__global__ __launch_bounds__(256, 1) void attn_kernel() {
    extern __shared__ __nv_bfloat16 sb[];
    const uint32_t sb_u = smem_to_u32(sb);

    const int tid = threadIdx.x, lane = tid & 31, warp = tid >> 5;
    const int kp = lane & 3, r4 = lane >> 2;
    const int l16 = lane & 15, lhi = lane >> 4;
    const int bh_idx = blockIdx.y;
    const int q0 = (gridDim.x - 1 - blockIdx.x) * 128;  // heavy-first
    const __nv_bfloat16* Qh_g = g_qh + (size_t)bh_idx * T_SEQ * HD;
    const __nv_bfloat16* Ql_g = g_ql + (size_t)bh_idx * T_SEQ * HD;
    const __nv_bfloat16* Kh_g = g_kh + (size_t)bh_idx * T_SEQ * HD;
    const __nv_bfloat16* Kl_g = g_kl + (size_t)bh_idx * T_SEQ * HD;
    const __nv_bfloat16* Vh_g = g_vh + (size_t)bh_idx * T_SEQ * HD;
    const __nv_bfloat16* Vl_g = g_vl + (size_t)bh_idx * T_SEQ * HD;

    // K/V staging: 128 rows x 8 chunks; thread covers 4 consecutive chunks
    const int krow = tid >> 1, kch = (tid & 1) * 4;
    const uint32_t kvoff = (uint32_t)krow * 144 + (uint32_t)kch * 16;

    const int ntiles = (q0 >> 7) + 1;  // 128-key tiles

    auto issue_kv = [&](int kt, int stg) {
        const uint32_t base = sb_u + 36864 + (uint32_t)stg * 73728;
        const size_t rs = (size_t)(kt * 128 + krow) * HD + kch * 8;
#pragma unroll
        for (int c = 0; c < 4; c++) {
            CP16(base + kvoff + c * 16, Kh_g + rs + c * 8);
            CP16(base + 18432 + kvoff + c * 16, Kl_g + rs + c * 8);
            CP16(base + 36864 + kvoff + c * 16, Vh_g + rs + c * 8);
            CP16(base + 55296 + kvoff + c * 16, Vl_g + rs + c * 8);
        }
    };

    // --- prologue: Q (with stage 0) + stage 1 ---
    {
#pragma unroll
        for (int i = 0; i < 4; i++) {
            int unit = tid + i * 256;
            int row = unit >> 3, c = unit & 7;
            uint32_t d = (uint32_t)row * 144 + (uint32_t)c * 16;
            CP16(sb_u + d, Qh_g + (size_t)(q0 + row) * HD + c * 8);
            CP16(sb_u + 18432 + d, Ql_g + (size_t)(q0 + row) * HD + c * 8);
        }
        issue_kv(0, 0);
        CP_COMMIT();
        if (ntiles > 1) issue_kv(1, 1);
        CP_COMMIT();
    }

    const uint32_t qbaseH = sb_u + (uint32_t)(warp * 16 + l16) * 144 + lhi * 16;
    const uint32_t qbaseL = qbaseH + 18432;
    const uint32_t frag_kv = (uint32_t)l16 * 144 + lhi * 16;

    float o[8][4];
#pragma unroll
    for (int j = 0; j < 8; j++)
#pragma unroll
        for (int r = 0; r < 4; r++) o[j][r] = 0.f;
    float mA = -1e30f, mB = -1e30f, lA = 0.f, lB = 0.f;

    const int rA = q0 + warp * 16 + r4;
    const int rB = rA + 8;

    // wait for Q + stage 0, hoist loop-invariant Q fragments (32 regs)
    CP_WAIT(1);
    __syncthreads();
    uint32_t qh[4][4], ql[4][4];
#pragma unroll
    for (int ks = 0; ks < 4; ks++) {
        LDSM4(qh[ks], qbaseH + ks * 32);
        LDSM4(ql[ks], qbaseL + ks * 32);
    }

    for (int kt = 0; kt < ntiles; kt++) {
        const int kt0 = kt << 7;
        if (kt > 0) {
            CP_WAIT(1);
            __syncthreads();
        }

        const uint32_t stb = sb_u + 36864 + (uint32_t)(kt & 1) * 73728;
        const uint32_t kbufH = stb + frag_kv;
        const uint32_t kbufL = stb + 18432 + frag_kv;
        const uint32_t vbufH = stb + 36864 + frag_kv;
        const uint32_t vbufL = stb + 55296 + frag_kv;

        // S = Q * K^T  (16 x 128 per warp; 16 j-blocks of 8 keys)
        float s[16][4];
#pragma unroll
        for (int j = 0; j < 16; j++)
#pragma unroll
            for (int r = 0; r < 4; r++) s[j][r] = 0.f;

#pragma unroll
        for (int ks = 0; ks < 4; ks++) {
            const uint32_t ko = ks * 32;
#pragma unroll
            for (int half = 0; half < 2; half++) {
                uint32_t kh[4][4], kl[4][4];
#pragma unroll
                for (int jp = 0; jp < 4; jp++) {
                    LDSM4(kh[jp], kbufH + (half * 4 + jp) * 2304 + ko);
                    LDSM4(kl[jp], kbufL + (half * 4 + jp) * 2304 + ko);
                }
#pragma unroll
                for (int j2 = 0; j2 < 8; j2++) {
                    const int jp = j2 >> 1, sel = j2 & 1;
                    mma16(s[half * 8 + j2], qh[ks][0], qh[ks][1], qh[ks][2], qh[ks][3],
                          kh[jp][sel], kh[jp][2 + sel]);
                }
#pragma unroll
                for (int j2 = 0; j2 < 8; j2++) {
                    const int jp = j2 >> 1, sel = j2 & 1;
                    mma16(s[half * 8 + j2], qh[ks][0], qh[ks][1], qh[ks][2], qh[ks][3],
                          kl[jp][sel], kl[jp][2 + sel]);
                }
#pragma unroll
                for (int j2 = 0; j2 < 8; j2++) {
                    const int jp = j2 >> 1, sel = j2 & 1;
                    mma16(s[half * 8 + j2], ql[ks][0], ql[ks][1], ql[ks][2], ql[ks][3],
                          kh[jp][sel], kh[jp][2 + sel]);
                }
            }
        }

        // Causal mask (last tile only)
        if (kt0 + 127 > q0) {
#pragma unroll
            for (int j = 0; j < 16; j++) {
                int c = kt0 + j * 8 + kp * 2;
                if (c > rA) s[j][0] = -1e30f;
                if (c + 1 > rA) s[j][1] = -1e30f;
                if (c > rB) s[j][2] = -1e30f;
                if (c + 1 > rB) s[j][3] = -1e30f;
            }
        }

        // Online softmax (one pass per 128 keys)
        float tA = -1e30f, tB = -1e30f;
#pragma unroll
        for (int j = 0; j < 16; j++) {
            tA = fmaxf(tA, fmaxf(s[j][0], s[j][1]));
            tB = fmaxf(tB, fmaxf(s[j][2], s[j][3]));
        }
        tA = fmaxf(tA, __shfl_xor_sync(0xffffffffu, tA, 1));
        tA = fmaxf(tA, __shfl_xor_sync(0xffffffffu, tA, 2));
        tB = fmaxf(tB, __shfl_xor_sync(0xffffffffu, tB, 1));
        tB = fmaxf(tB, __shfl_xor_sync(0xffffffffu, tB, 2));
        float mAn = fmaxf(mA, tA), mBn = fmaxf(mB, tB);
        float aA = __expf(mA - mAn), aB = __expf(mB - mBn);
        mA = mAn; mB = mBn;
        lA *= aA; lB *= aB;

        // P packed back into the dead S registers
#pragma unroll
        for (int j = 0; j < 16; j++) {
            float p0 = __expf(s[j][0] - mA), p1 = __expf(s[j][1] - mA);
            float p2 = __expf(s[j][2] - mB), p3 = __expf(s[j][3] - mB);
            lA += p0 + p1;
            lB += p2 + p3;
            uint32_t hp01, lp01, hp23, lp23;
            bsplit2(p0, p1, hp01, lp01);
            bsplit2(p2, p3, hp23, lp23);
            s[j][0] = __uint_as_float(hp01);
            s[j][1] = __uint_as_float(hp23);
            s[j][2] = __uint_as_float(lp01);
            s[j][3] = __uint_as_float(lp23);
        }
#pragma unroll
        for (int j = 0; j < 8; j++) {
            o[j][0] *= aA; o[j][1] *= aA; o[j][2] *= aB; o[j][3] *= aB;
        }

        // O += P * V  (contraction over 128 keys = 8 k16 steps)
#pragma unroll
        for (int ks = 0; ks < 8; ks++) {
            uint32_t ah0 = __float_as_uint(s[2 * ks][0]);
            uint32_t ah1 = __float_as_uint(s[2 * ks][1]);
            uint32_t ah2 = __float_as_uint(s[2 * ks + 1][0]);
            uint32_t ah3 = __float_as_uint(s[2 * ks + 1][1]);
            uint32_t al0 = __float_as_uint(s[2 * ks][2]);
            uint32_t al1 = __float_as_uint(s[2 * ks][3]);
            uint32_t al2 = __float_as_uint(s[2 * ks + 1][2]);
            uint32_t al3 = __float_as_uint(s[2 * ks + 1][3]);
            uint32_t vh[4][4], vl[4][4];
#pragma unroll
            for (int jp = 0; jp < 4; jp++) {
                LDSM4T(vh[jp], vbufH + ks * 2304 + jp * 32);
                LDSM4T(vl[jp], vbufL + ks * 2304 + jp * 32);
            }
#pragma unroll
            for (int j = 0; j < 8; j++) {
                const int jp = j >> 1, sel = j & 1;
                mma16(o[j], ah0, ah1, ah2, ah3, vh[jp][2 * sel], vh[jp][2 * sel + 1]);
            }
#pragma unroll
            for (int j = 0; j < 8; j++) {
                const int jp = j >> 1, sel = j & 1;
                mma16(o[j], ah0, ah1, ah2, ah3, vl[jp][2 * sel], vl[jp][2 * sel + 1]);
            }
#pragma unroll
            for (int j = 0; j < 8; j++) {
                const int jp = j >> 1, sel = j & 1;
                mma16(o[j], al0, al1, al2, al3, vh[jp][2 * sel], vh[jp][2 * sel + 1]);
            }
        }

        // recycle this buffer, then prefetch kt+2
        __syncthreads();
        if (kt + 2 < ntiles) issue_kv(kt + 2, kt & 1);
        CP_COMMIT();
    }

    lA += __shfl_xor_sync(0xffffffffu, lA, 1);
    lA += __shfl_xor_sync(0xffffffffu, lA, 2);
    lB += __shfl_xor_sync(0xffffffffu, lB, 1);
    lB += __shfl_xor_sync(0xffffffffu, lB, 2);
    float iA = 1.f / lA, iB = 1.f / lB;

    const int b = bh_idx >> 4, h = bh_idx & 15;
    const int tokA = b * T_SEQ + rA;
#pragma unroll
    for (int j = 0; j < 8; j++) {
        int col = h * 64 + j * 8 + kp * 2;
        size_t oA = (size_t)tokA * CDIM + col;
        size_t oB = (size_t)(tokA + 8) * CDIM + col;
        uint32_t hp, lp;
        bsplit2(o[j][0] * iA, o[j][1] * iA, hp, lp);
        *reinterpret_cast<uint32_t*>(g_yh + oA) = hp;
        *reinterpret_cast<uint32_t*>(g_yl + oA) = lp;
        bsplit2(o[j][2] * iB, o[j][3] * iB, hp, lp);
        *reinterpret_cast<uint32_t*>(g_yh + oB) = hp;
        *reinterpret_cast<uint32_t*>(g_yl + oB) = lp;
    }
}

// ---------------- launch ----------------
extern "C" void kernel_launch(void* const* d_in, const int* in_sizes, int n_in,
                              void* d_out, int out_size) {
    const float* x    = (const float*)d_in[0];
    const float* Wqkv = (const float*)d_in[1];
    const float* bqkv = (const float*)d_in[2];
    const float* Wp   = (const float*)d_in[3];
    const float* bp   = (const float*)d_in[4];
    float* out = (float*)d_out;

    void *xh, *xl, *wh, *wl, *wph, *wpl, *yh, *yl;
    cudaGetSymbolAddress(&xh, g_xh);   cudaGetSymbolAddress(&xl, g_xl);
    cudaGetSymbolAddress(&wh, g_wh);   cudaGetSymbolAddress(&wl, g_wl);
    cudaGetSymbolAddress(&wph, g_wph); cudaGetSymbolAddress(&wpl, g_wpl);
    cudaGetSymbolAddress(&yh, g_yh);   cudaGetSymbolAddress(&yl, g_yl);

    cudaFuncSetAttribute(attn_kernel, cudaFuncAttributeMaxDynamicSharedMemorySize,
                         ATT_SMEM_BYTES);
    cudaFuncSetAttribute(gemm_bf16<3 * CDIM, 0>, cudaFuncAttributeMaxDynamicSharedMemorySize,
                         GEMM_SMEM_BYTES);
    cudaFuncSetAttribute(gemm_bf16<CDIM, 1>, cudaFuncAttributeMaxDynamicSharedMemorySize,
                         GEMM_SMEM_BYTES);

    // 0) pre-split inputs/weights
    xsplit_kernel<<<(MROWS * CDIM / 4) / 256, 256>>>(x, (__nv_bfloat16*)xh, (__nv_bfloat16*)xl);
    wsplit_kernel<<<dim3(3 * CDIM / 32, CDIM / 32), dim3(32, 8)>>>(
        Wqkv, (__nv_bfloat16*)wh, (__nv_bfloat16*)wl, 3 * CDIM);
    wsplit_kernel<<<dim3(CDIM / 32, CDIM / 32), dim3(32, 8)>>>(
        Wp, (__nv_bfloat16*)wph, (__nv_bfloat16*)wpl, CDIM);

    // 1) QKV projection -> pre-split bf16 g_q*/g_k*/g_v*
    gemm_bf16<3 * CDIM, 0><<<dim3(MROWS / 128, 3 * CDIM / 128), 512, GEMM_SMEM_BYTES>>>(
        (const __nv_bfloat16*)xh, (const __nv_bfloat16*)xl,
        (const __nv_bfloat16*)wh, (const __nv_bfloat16*)wl, bqkv, nullptr);

    // 2) causal flash attention -> g_yh/g_yl (pre-split)
    attn_kernel<<<dim3(T_SEQ / 128, BSZ * NHEAD), 256, ATT_SMEM_BYTES>>>();

    // 3) output projection -> d_out
    gemm_bf16<CDIM, 1><<<dim3(MROWS / 128, CDIM / 128), 512, GEMM_SMEM_BYTES>>>(
        (const __nv_bfloat16*)yh, (const __nv_bfloat16*)yl,
        (const __nv_bfloat16*)wph, (const __nv_bfloat16*)wpl, bp, out);
}

// round 17
// speedup vs baseline: 1.0443x; 1.0443x over previous
#include <cuda_runtime.h>
#include <cuda_bf16.h>
#include <cstdint>

#define T_SEQ 2048
#define NHEAD 16
#define HD 64
#define CDIM 1024
#define BSZ 4
#define MROWS 8192

// ---------------- device scratch (allocation-free rule) ----------------
#define QKV_ELEMS ((size_t)BSZ * NHEAD * T_SEQ * HD)
__device__ __align__(128) __nv_bfloat16 g_qh[QKV_ELEMS], g_ql[QKV_ELEMS];
__device__ __align__(128) __nv_bfloat16 g_kh[QKV_ELEMS], g_kl[QKV_ELEMS];
__device__ __align__(128) __nv_bfloat16 g_vh[QKV_ELEMS], g_vl[QKV_ELEMS];
__device__ __align__(128) __nv_bfloat16 g_xh[(size_t)MROWS * CDIM], g_xl[(size_t)MROWS * CDIM];
__device__ __align__(128) __nv_bfloat16 g_wh[(size_t)3 * CDIM * CDIM], g_wl[(size_t)3 * CDIM * CDIM];
__device__ __align__(128) __nv_bfloat16 g_wph[(size_t)CDIM * CDIM], g_wpl[(size_t)CDIM * CDIM];
__device__ __align__(128) __nv_bfloat16 g_yh[(size_t)MROWS * CDIM], g_yl[(size_t)MROWS * CDIM];

// ---------------- helpers ----------------
__device__ __forceinline__ uint32_t smem_to_u32(const void* p) {
    uint32_t a;
    asm("{ .reg .u64 t; cvta.to.shared.u64 t, %1; cvt.u32.u64 %0, t; }" : "=r"(a) : "l"(p));
    return a;
}

#define LDSM4(r, addr) \
    asm volatile("ldmatrix.sync.aligned.m8n8.x4.shared.b16 {%0,%1,%2,%3}, [%4];" \
                 : "=r"((r)[0]), "=r"((r)[1]), "=r"((r)[2]), "=r"((r)[3]) : "r"(addr))
#define LDSM4T(r, addr) \
    asm volatile("ldmatrix.sync.aligned.m8n8.x4.trans.shared.b16 {%0,%1,%2,%3}, [%4];" \
                 : "=r"((r)[0]), "=r"((r)[1]), "=r"((r)[2]), "=r"((r)[3]) : "r"(addr))
#define CP16(dst, src) \
    asm volatile("cp.async.cg.shared.global [%0], [%1], 16;" :: "r"(dst), "l"(src))
#define CP_COMMIT() asm volatile("cp.async.commit_group;" ::: "memory")
#define CP_WAIT(n) asm volatile("cp.async.wait_group %0;" :: "n"(n) : "memory")

__device__ __forceinline__ void bsplit(float x, __nv_bfloat16& h, __nv_bfloat16& l) {
    h = __float2bfloat16_rn(x);
    l = __float2bfloat16_rn(x - __bfloat162float(h));
}
__device__ __forceinline__ void bsplit2(float x, float y, uint32_t& hp, uint32_t& lp) {
    __nv_bfloat162 hb = __floats2bfloat162_rn(x, y);
    float hx = __bfloat162float(__low2bfloat16(hb));
    float hy = __bfloat162float(__high2bfloat16(hb));
    __nv_bfloat162 lb = __floats2bfloat162_rn(x - hx, y - hy);
    hp = *reinterpret_cast<uint32_t*>(&hb);
    lp = *reinterpret_cast<uint32_t*>(&lb);
}

__device__ __forceinline__ void mma16(float c[4],
                                      uint32_t a0, uint32_t a1, uint32_t a2, uint32_t a3,
                                      uint32_t b0, uint32_t b1) {
    asm("mma.sync.aligned.m16n8k16.row.col.f32.bf16.bf16.f32 "
        "{%0,%1,%2,%3}, {%4,%5,%6,%7}, {%8,%9}, {%0,%1,%2,%3};\n"
        : "+f"(c[0]), "+f"(c[1]), "+f"(c[2]), "+f"(c[3])
        : "r"(a0), "r"(a1), "r"(a2), "r"(a3), "r"(b0), "r"(b1));
}

// QKV epilogue: write pre-split bf16 h/l, Q scaled by 1/8
__device__ __forceinline__ void qkv_store_bf(int m, int n, float v0, float v1) {
    int part = n >> 10;
    int cc = n & 1023;
    int h = cc >> 6, d = cc & 63;
    int b = m >> 11, t = m & 2047;
    if (part == 0) { v0 *= 0.125f; v1 *= 0.125f; }
    __nv_bfloat16* dh = (part == 0) ? g_qh : (part == 1) ? g_kh : g_vh;
    __nv_bfloat16* dl = (part == 0) ? g_ql : (part == 1) ? g_kl : g_vl;
    size_t off = ((((size_t)b * NHEAD + h) * T_SEQ + t) << 6) + d;
    uint32_t hp, lp;
    bsplit2(v0, v1, hp, lp);
    *reinterpret_cast<uint32_t*>(dh + off) = hp;
    *reinterpret_cast<uint32_t*>(dl + off) = lp;
}

// ---------------------------------------------------------------------------
// Merged pre-split kernel: one launch does X-split + Wqkv transpose-split +
// Wp transpose-split (block ranges: [0,8192) X, [8192,11264) Wqkv,
// [11264,12288) Wp). 256 threads everywhere.
// ---------------------------------------------------------------------------
__global__ void presplit_all(const float* __restrict__ X,
                             const float* __restrict__ Wqkv,
                             const float* __restrict__ Wp) {
    __shared__ float tile[32][33];
    const int tid = threadIdx.x;
    const int b = blockIdx.x;

    if (b < 8192) {
        // X split: each thread handles one float4
        int i = b * 256 + tid;
        float4 v = reinterpret_cast<const float4*>(X)[i];
        uint32_t h01, l01, h23, l23;
        bsplit2(v.x, v.y, h01, l01);
        bsplit2(v.z, v.w, h23, l23);
        reinterpret_cast<uint2*>(g_xh)[i] = make_uint2(h01, h23);
        reinterpret_cast<uint2*>(g_xl)[i] = make_uint2(l01, l23);
        return;
    }

    // W transpose + split: W[1024, N] fp32 -> Wh/Wl [N, 1024] bf16
    const float* W;
    __nv_bfloat16 *Wh, *Wl;
    int N, nb, kb;
    if (b < 8192 + 3072) {
        int bb = b - 8192;
        W = Wqkv; Wh = g_wh; Wl = g_wl; N = 3 * CDIM;
        nb = (bb % 96) * 32;
        kb = (bb / 96) * 32;
    } else {
        int bb = b - 11264;
        W = Wp; Wh = g_wph; Wl = g_wpl; N = CDIM;
        nb = (bb % 32) * 32;
        kb = (bb / 32) * 32;
    }
    const int tx = tid & 31, ty = tid >> 5;  // (32, 8)
#pragma unroll
    for (int r = 0; r < 32; r += 8)
        tile[ty + r][tx] = W[(size_t)(kb + ty + r) * N + nb + tx];
    __syncthreads();
#pragma unroll
    for (int r = 0; r < 32; r += 8) {
        float v = tile[tx][ty + r];
        __nv_bfloat16 h, l;
        bsplit(v, h, l);
        size_t o = (size_t)(nb + ty + r) * CDIM + kb + tx;
        Wh[o] = h;
        Wl[o] = l;
    }
}

// ---------------------------------------------------------------------------
// bf16 3-term GEMM (LOCKED: exact R8 config, best measured 467 us).
// CTA 128x128, 16 warps 32x32, BK=32, LDG reg-prefetch + double-buffered smem,
// LDSM fragments, term-major MMA order. Rows padded to 40 bf16 (80 B).
// ---------------------------------------------------------------------------
#define GEMM_SMEM_BYTES (2 * 40960)  // 81920

template <int NTOT, int MODE>
__global__ __launch_bounds__(512, 1) void gemm_bf16(
    const __nv_bfloat16* __restrict__ Ah_g, const __nv_bfloat16* __restrict__ Al_g,
    const __nv_bfloat16* __restrict__ Bh_g, const __nv_bfloat16* __restrict__ Bl_g,
    const float* __restrict__ bias, float* __restrict__ out) {
    extern __shared__ char smem[];
    const uint32_t sb_u = smem_to_u32(smem);
    const int tid = threadIdx.x, lane = tid & 31, warp = tid >> 5;
    const int wm = (warp >> 2) * 32, wn = (warp & 3) * 32;
    const int m0 = blockIdx.x * 128, n0 = blockIdx.y * 128;
    const int kp = lane & 3, r4 = lane >> 2;
    const int l16 = lane & 15, lhi = lane >> 4;

    const uint32_t a_fa = (uint32_t)(wm + l16) * 80 + lhi * 16;
    const uint32_t b_fa = (uint32_t)(wn + l16) * 80 + lhi * 16;

    const int lr = tid >> 2, ch = tid & 3;
    const uint32_t sbyte = (uint32_t)lr * 80 + (uint32_t)ch * 16;
    const __nv_bfloat16* pAh = Ah_g + (size_t)(m0 + lr) * CDIM + ch * 8;
    const __nv_bfloat16* pAl = Al_g + (size_t)(m0 + lr) * CDIM + ch * 8;
    const __nv_bfloat16* pBh = Bh_g + (size_t)(n0 + lr) * CDIM + ch * 8;
    const __nv_bfloat16* pBl = Bl_g + (size_t)(n0 + lr) * CDIM + ch * 8;

    float acc[2][4][4];
#pragma unroll
    for (int i = 0; i < 2; i++)
#pragma unroll
        for (int j = 0; j < 4; j++)
#pragma unroll
            for (int r = 0; r < 4; r++) acc[i][j][r] = 0.f;

    uint4 va, vb, vc, vd;
    va = *reinterpret_cast<const uint4*>(pAh);
    vb = *reinterpret_cast<const uint4*>(pAl);
    vc = *reinterpret_cast<const uint4*>(pBh);
    vd = *reinterpret_cast<const uint4*>(pBl);
    *reinterpret_cast<uint4*>(smem + sbyte) = va;
    *reinterpret_cast<uint4*>(smem + 10240 + sbyte) = vb;
    *reinterpret_cast<uint4*>(smem + 20480 + sbyte) = vc;
    *reinterpret_cast<uint4*>(smem + 30720 + sbyte) = vd;
    __syncthreads();

    const int NK = CDIM / 32;
    for (int kt = 0; kt < NK; kt++) {
        const int buf = kt & 1;
        const bool more = (kt + 1 < NK);
        if (more) {
            const int kk = (kt + 1) * 32;
            va = *reinterpret_cast<const uint4*>(pAh + kk);
            vb = *reinterpret_cast<const uint4*>(pAl + kk);
            vc = *reinterpret_cast<const uint4*>(pBh + kk);
            vd = *reinterpret_cast<const uint4*>(pBl + kk);
        }

        const uint32_t base_u = sb_u + buf * 40960;
#pragma unroll
        for (int ks = 0; ks < 2; ks++) {
            const uint32_t ko = ks * 32;
            uint32_t ah[2][4], al[2][4], bh[2][4], bl[2][4];
#pragma unroll
            for (int i = 0; i < 2; i++) {
                LDSM4(ah[i], base_u + a_fa + i * 1280 + ko);
                LDSM4(al[i], base_u + 10240 + a_fa + i * 1280 + ko);
            }
#pragma unroll
            for (int jp = 0; jp < 2; jp++) {
                LDSM4(bh[jp], base_u + 20480 + b_fa + jp * 1280 + ko);
                LDSM4(bl[jp], base_u + 30720 + b_fa + jp * 1280 + ko);
            }
            // term-major: all hh, then all hl, then all lh
#pragma unroll
            for (int j = 0; j < 4; j++) {
                const int jp = j >> 1, sel = j & 1;
#pragma unroll
                for (int i = 0; i < 2; i++)
                    mma16(acc[i][j], ah[i][0], ah[i][1], ah[i][2], ah[i][3],
                          bh[jp][sel], bh[jp][2 + sel]);
            }
#pragma unroll
            for (int j = 0; j < 4; j++) {
                const int jp = j >> 1, sel = j & 1;
#pragma unroll
                for (int i = 0; i < 2; i++)
                    mma16(acc[i][j], ah[i][0], ah[i][1], ah[i][2], ah[i][3],
                          bl[jp][sel], bl[jp][2 + sel]);
            }
#pragma unroll
            for (int j = 0; j < 4; j++) {
                const int jp = j >> 1, sel = j & 1;
#pragma unroll
                for (int i = 0; i < 2; i++)
                    mma16(acc[i][j], al[i][0], al[i][1], al[i][2], al[i][3],
                          bh[jp][sel], bh[jp][2 + sel]);
            }
        }

        if (more) {
            char* nb2 = smem + (1 - buf) * 40960;
            *reinterpret_cast<uint4*>(nb2 + sbyte) = va;
            *reinterpret_cast<uint4*>(nb2 + 10240 + sbyte) = vb;
            *reinterpret_cast<uint4*>(nb2 + 20480 + sbyte) = vc;
            *reinterpret_cast<uint4*>(nb2 + 30720 + sbyte) = vd;
        }
        __syncthreads();
    }

    // Epilogue
#pragma unroll
    for (int i = 0; i < 2; i++) {
        int row = m0 + wm + i * 16 + r4;
#pragma unroll
        for (int j = 0; j < 4; j++) {
            int col = n0 + wn + j * 8 + kp * 2;
            float b0 = bias[col], b1 = bias[col + 1];
            float v00 = acc[i][j][0] + b0, v01 = acc[i][j][1] + b1;
            float v10 = acc[i][j][2] + b0, v11 = acc[i][j][3] + b1;
            if (MODE == 0) {
                qkv_store_bf(row, col, v00, v01);
                qkv_store_bf(row + 8, col, v10, v11);
            } else {
                *reinterpret_cast<float2*>(out + (size_t)row * NTOT + col) = make_float2(v00, v01);
                *reinterpret_cast<float2*>(out + (size_t)(row + 8) * NTOT + col) = make_float2(v10, v11);
            }
        }
    }
}

// ---------------------------------------------------------------------------
// Flash attention (R15 champion config): causal, bf16 3-term, pre-split
// inputs, cp.async 2-stage K/V ring, heavy-first q order, Q fragments
// hoisted into registers, ldmatrix (V via .trans), term-major MMA order.
// ---------------------------------------------------------------------------
#define ATT_SMEM_BYTES 110592  // Q 36864 + 2 stages x 36864

__global__ __launch_bounds__(256, 1) void attn_kernel() {
    extern __shared__ __nv_bfloat16 sb[];
    const uint32_t sb_u = smem_to_u32(sb);

    const int tid = threadIdx.x, lane = tid & 31, warp = tid >> 5;
    const int kp = lane & 3, r4 = lane >> 2;
    const int l16 = lane & 15, lhi = lane >> 4;
    const int bh_idx = blockIdx.y;
    // heavy-first: largest q-blocks (most key tiles) launch first
    const int q0 = (gridDim.x - 1 - blockIdx.x) * 128;
    const __nv_bfloat16* Qh_g = g_qh + (size_t)bh_idx * T_SEQ * HD;
    const __nv_bfloat16* Ql_g = g_ql + (size_t)bh_idx * T_SEQ * HD;
    const __nv_bfloat16* Kh_g = g_kh + (size_t)bh_idx * T_SEQ * HD;
    const __nv_bfloat16* Kl_g = g_kl + (size_t)bh_idx * T_SEQ * HD;
    const __nv_bfloat16* Vh_g = g_vh + (size_t)bh_idx * T_SEQ * HD;
    const __nv_bfloat16* Vl_g = g_vl + (size_t)bh_idx * T_SEQ * HD;

    const int krow = tid >> 2, kch = tid & 3;
    const uint32_t kvoff = (uint32_t)krow * 144 + (uint32_t)kch * 16;

    const int ntiles = (q0 >> 6) + 2;

    // stage loader (K/V tile kt into buffer stg)
    auto issue_kv = [&](int kt, int stg) {
        const uint32_t base = sb_u + 36864 + (uint32_t)stg * 36864;
        const size_t rs = (size_t)(kt * 64 + krow) * HD + kch * 8;
        CP16(base + kvoff, Kh_g + rs);
        CP16(base + kvoff + 64, Kh_g + rs + 32);
        CP16(base + 9216 + kvoff, Kl_g + rs);
        CP16(base + 9216 + kvoff + 64, Kl_g + rs + 32);
        CP16(base + 18432 + kvoff, Vh_g + rs);
        CP16(base + 18432 + kvoff + 64, Vh_g + rs + 32);
        CP16(base + 27648 + kvoff, Vl_g + rs);
        CP16(base + 27648 + kvoff + 64, Vl_g + rs + 32);
    };

    // --- prologue: Q + stage 0 (group 0), stage 1 (group 1) ---
    {
#pragma unroll
        for (int i = 0; i < 4; i++) {
            int unit = tid + i * 256;
            int row = unit >> 3, c = unit & 7;
            uint32_t d = (uint32_t)row * 144 + (uint32_t)c * 16;
            CP16(sb_u + d, Qh_g + (size_t)(q0 + row) * HD + c * 8);
            CP16(sb_u + 18432 + d, Ql_g + (size_t)(q0 + row) * HD + c * 8);
        }
        issue_kv(0, 0);
        CP_COMMIT();
        issue_kv(1, 1);
        CP_COMMIT();
    }

    const uint32_t qbaseH = sb_u + (uint32_t)(warp * 16 + l16) * 144 + lhi * 16;
    const uint32_t qbaseL = qbaseH + 18432;
    const uint32_t frag_kv = (uint32_t)l16 * 144 + lhi * 16;

    float o[8][4];
#pragma unroll
    for (int j = 0; j < 8; j++)
#pragma unroll
        for (int r = 0; r < 4; r++) o[j][r] = 0.f;
    float mA = -1e30f, mB = -1e30f, lA = 0.f, lB = 0.f;

    const int rA = q0 + warp * 16 + r4;
    const int rB = rA + 8;

    // wait for Q + stage 0, then hoist loop-invariant Q fragments (32 regs)
    CP_WAIT(1);
    __syncthreads();
    uint32_t qh[4][4], ql[4][4];
#pragma unroll
    for (int ks = 0; ks < 4; ks++) {
        LDSM4(qh[ks], qbaseH + ks * 32);
        LDSM4(ql[ks], qbaseL + ks * 32);
    }

    for (int kt = 0; kt < ntiles; kt++) {
        const int kt0 = kt << 6;
        if (kt > 0) {
            CP_WAIT(1);
            __syncthreads();
        }

        const uint32_t stb = sb_u + 36864 + (uint32_t)(kt & 1) * 36864;
        const uint32_t kbufH = stb + frag_kv;
        const uint32_t kbufL = stb + 9216 + frag_kv;
        const uint32_t vbufH = stb + 18432 + frag_kv;
        const uint32_t vbufL = stb + 27648 + frag_kv;

        // S = Q * K^T (Q fragments already in registers)
        float s[8][4];
#pragma unroll
        for (int j = 0; j < 8; j++)
#pragma unroll
            for (int r = 0; r < 4; r++) s[j][r] = 0.f;

#pragma unroll
        for (int ks = 0; ks < 4; ks++) {
            const uint32_t ko = ks * 32;
            uint32_t kh[4][4], kl[4][4];
#pragma unroll
            for (int jp = 0; jp < 4; jp++) {
                LDSM4(kh[jp], kbufH + jp * 2304 + ko);
                LDSM4(kl[jp], kbufL + jp * 2304 + ko);
            }
#pragma unroll
            for (int j = 0; j < 8; j++) {
                const int jp = j >> 1, sel = j & 1;
                mma16(s[j], qh[ks][0], qh[ks][1], qh[ks][2], qh[ks][3],
                      kh[jp][sel], kh[jp][2 + sel]);
            }
#pragma unroll
            for (int j = 0; j < 8; j++) {
                const int jp = j >> 1, sel = j & 1;
                mma16(s[j], qh[ks][0], qh[ks][1], qh[ks][2], qh[ks][3],
                      kl[jp][sel], kl[jp][2 + sel]);
            }
#pragma unroll
            for (int j = 0; j < 8; j++) {
                const int jp = j >> 1, sel = j & 1;
                mma16(s[j], ql[ks][0], ql[ks][1], ql[ks][2], ql[ks][3],
                      kh[jp][sel], kh[jp][2 + sel]);
            }
        }

        if (kt0 + 63 > q0) {
#pragma unroll
            for (int j = 0; j < 8; j++) {
                int c = kt0 + j * 8 + kp * 2;
                if (c > rA) s[j][0] = -1e30f;
                if (c + 1 > rA) s[j][1] = -1e30f;
                if (c > rB) s[j][2] = -1e30f;
                if (c + 1 > rB) s[j][3] = -1e30f;
            }
        }

        float tA = -1e30f, tB = -1e30f;
#pragma unroll
        for (int j = 0; j < 8; j++) {
            tA = fmaxf(tA, fmaxf(s[j][0], s[j][1]));
            tB = fmaxf(tB, fmaxf(s[j][2], s[j][3]));
        }
        tA = fmaxf(tA, __shfl_xor_sync(0xffffffffu, tA, 1));
        tA = fmaxf(tA, __shfl_xor_sync(0xffffffffu, tA, 2));
        tB = fmaxf(tB, __shfl_xor_sync(0xffffffffu, tB, 1));
        tB = fmaxf(tB, __shfl_xor_sync(0xffffffffu, tB, 2));
        float mAn = fmaxf(mA, tA), mBn = fmaxf(mB, tB);
        float aA = __expf(mA - mAn), aB = __expf(mB - mBn);
        mA = mAn; mB = mBn;
        lA *= aA; lB *= aB;

        uint32_t ph01[8], ph23[8], pl01[8], pl23[8];
#pragma unroll
        for (int j = 0; j < 8; j++) {
            float p0 = __expf(s[j][0] - mA), p1 = __expf(s[j][1] - mA);
            float p2 = __expf(s[j][2] - mB), p3 = __expf(s[j][3] - mB);
            lA += p0 + p1;
            lB += p2 + p3;
            o[j][0] *= aA; o[j][1] *= aA; o[j][2] *= aB; o[j][3] *= aB;
            bsplit2(p0, p1, ph01[j], pl01[j]);
            bsplit2(p2, p3, ph23[j], pl23[j]);
        }

        // O += P * V (V row-major, fragments via ldmatrix.trans), term-major
#pragma unroll
        for (int ks = 0; ks < 4; ks++) {
            uint32_t ah0 = ph01[2 * ks],     ah1 = ph23[2 * ks];
            uint32_t ah2 = ph01[2 * ks + 1], ah3 = ph23[2 * ks + 1];
            uint32_t al0 = pl01[2 * ks],     al1 = pl23[2 * ks];
            uint32_t al2 = pl01[2 * ks + 1], al3 = pl23[2 * ks + 1];
            uint32_t vh[4][4], vl[4][4];
#pragma unroll
            for (int jp = 0; jp < 4; jp++) {
                LDSM4T(vh[jp], vbufH + ks * 2304 + jp * 32);
                LDSM4T(vl[jp], vbufL + ks * 2304 + jp * 32);
            }
#pragma unroll
            for (int j = 0; j < 8; j++) {
                const int jp = j >> 1, sel = j & 1;
                mma16(o[j], ah0, ah1, ah2, ah3, vh[jp][2 * sel], vh[jp][2 * sel + 1]);
            }
#pragma unroll
            for (int j = 0; j < 8; j++) {
                const int jp = j >> 1, sel = j & 1;
                mma16(o[j], ah0, ah1, ah2, ah3, vl[jp][2 * sel], vl[jp][2 * sel + 1]);
            }
#pragma unroll
            for (int j = 0; j < 8; j++) {
                const int jp = j >> 1, sel = j & 1;
                mma16(o[j], al0, al1, al2, al3, vh[jp][2 * sel], vh[jp][2 * sel + 1]);
            }
        }

        // recycle this buffer: all warps done reading, then prefetch kt+2
        __syncthreads();
        if (kt + 2 < ntiles) issue_kv(kt + 2, kt & 1);
        CP_COMMIT();
    }

    lA += __shfl_xor_sync(0xffffffffu, lA, 1);
    lA += __shfl_xor_sync(0xffffffffu, lA, 2);
    lB += __shfl_xor_sync(0xffffffffu, lB, 1);
    lB += __shfl_xor_sync(0xffffffffu, lB, 2);
    float iA = 1.f / lA, iB = 1.f / lB;

    const int b = bh_idx >> 4, h = bh_idx & 15;
    const int tokA = b * T_SEQ + rA;
#pragma unroll
    for (int j = 0; j < 8; j++) {
        int col = h * 64 + j * 8 + kp * 2;
        size_t oA = (size_t)tokA * CDIM + col;
        size_t oB = (size_t)(tokA + 8) * CDIM + col;
        uint32_t hp, lp;
        bsplit2(o[j][0] * iA, o[j][1] * iA, hp, lp);
        *reinterpret_cast<uint32_t*>(g_yh + oA) = hp;
        *reinterpret_cast<uint32_t*>(g_yl + oA) = lp;
        bsplit2(o[j][2] * iB, o[j][3] * iB, hp, lp);
        *reinterpret_cast<uint32_t*>(g_yh + oB) = hp;
        *reinterpret_cast<uint32_t*>(g_yl + oB) = lp;
    }
}

// ---------------- launch ----------------
extern "C" void kernel_launch(void* const* d_in, const int* in_sizes, int n_in,
                              void* d_out, int out_size) {
    const float* x    = (const float*)d_in[0];
    const float* Wqkv = (const float*)d_in[1];
    const float* bqkv = (const float*)d_in[2];
    const float* Wp   = (const float*)d_in[3];
    const float* bp   = (const float*)d_in[4];
    float* out = (float*)d_out;

    void *xh, *xl, *wh, *wl, *wph, *wpl, *yh, *yl;
    cudaGetSymbolAddress(&xh, g_xh);   cudaGetSymbolAddress(&xl, g_xl);
    cudaGetSymbolAddress(&wh, g_wh);   cudaGetSymbolAddress(&wl, g_wl);
    cudaGetSymbolAddress(&wph, g_wph); cudaGetSymbolAddress(&wpl, g_wpl);
    cudaGetSymbolAddress(&yh, g_yh);   cudaGetSymbolAddress(&yl, g_yl);

    cudaFuncSetAttribute(attn_kernel, cudaFuncAttributeMaxDynamicSharedMemorySize,
                         ATT_SMEM_BYTES);
    cudaFuncSetAttribute(gemm_bf16<3 * CDIM, 0>, cudaFuncAttributeMaxDynamicSharedMemorySize,
                         GEMM_SMEM_BYTES);
    cudaFuncSetAttribute(gemm_bf16<CDIM, 1>, cudaFuncAttributeMaxDynamicSharedMemorySize,
                         GEMM_SMEM_BYTES);

    // 0) merged pre-split (X + Wqkv + Wp) in ONE launch
    presplit_all<<<12288, 256>>>(x, Wqkv, Wp);

    // 1) QKV projection -> pre-split bf16 g_q*/g_k*/g_v*
    gemm_bf16<3 * CDIM, 0><<<dim3(MROWS / 128, 3 * CDIM / 128), 512, GEMM_SMEM_BYTES>>>(
        (const __nv_bfloat16*)xh, (const __nv_bfloat16*)xl,
        (const __nv_bfloat16*)wh, (const __nv_bfloat16*)wl, bqkv, nullptr);

    // 2) causal flash attention -> g_yh/g_yl (pre-split)
    attn_kernel<<<dim3(T_SEQ / 128, BSZ * NHEAD), 256, ATT_SMEM_BYTES>>>();

    // 3) output projection -> d_out
    gemm_bf16<CDIM, 1><<<dim3(MROWS / 128, CDIM / 128), 512, GEMM_SMEM_BYTES>>>(
        (const __nv_bfloat16*)yh, (const __nv_bfloat16*)yl,
        (const __nv_bfloat16*)wph, (const __nv_bfloat16*)wpl, bp, out);
}